// round 1
// baseline (speedup 1.0000x reference)
#include <cuda_runtime.h>
#include <math.h>

#define D_MODEL   256
#define N_HEADS   8
#define N_LEVELS  4
#define N_POINTS  4
#define HEAD_DIM  32
#define LEN_IN    5440
#define LEN_Q     5440
#define BATCH     4
#define M_TOTAL   (BATCH * LEN_Q)   // 21760 = 170 * 128

// ---------------- scratch (static device globals; no allocation) -------------
__device__ float g_value[(size_t)M_TOTAL * D_MODEL];   // value = in_flat @ W_val + b
__device__ float g_off  [(size_t)M_TOTAL * 256];       // sampling offsets (pre-reshape)
__device__ float g_attn [(size_t)M_TOTAL * 128];       // attention logits
__device__ float g_mid  [(size_t)M_TOTAL * D_MODEL];   // pre-output-proj result

// ---------------- fp32 SGEMM: C[M,N] = A[M,256] * W[256,N] + bias ------------
// BM=128, BN=128, BK=8, 256 threads, each thread 8x8. All dims divide exactly.
template <int N>
__global__ void __launch_bounds__(256)
sgemm_bias(const float* __restrict__ A, const float* __restrict__ W,
           const float* __restrict__ bias, float* __restrict__ C) {
    __shared__ float As[8][128];
    __shared__ float Bs[8][128];

    const int tid = threadIdx.x;
    const int bm  = blockIdx.x * 128;
    const int bn  = blockIdx.y * 128;
    const int tx  = tid & 15;       // 0..15 -> 8 cols each
    const int ty  = tid >> 4;       // 0..15 -> 8 rows each

    // A-tile load mapping: 128 rows x 8 cols, one float4 per thread
    const int arow = tid >> 1;            // 0..127
    const int acol = (tid & 1) * 4;       // 0 or 4
    // B-tile load mapping: 8 rows x 128 cols, one float4 per thread
    const int brow = tid >> 5;            // 0..7
    const int bcol = (tid & 31) * 4;      // 0..124

    const float* Ag = A + (size_t)(bm + arow) * D_MODEL + acol;
    const float* Wg = W + (size_t)brow * N + bn + bcol;

    float acc[8][8];
#pragma unroll
    for (int i = 0; i < 8; ++i)
#pragma unroll
        for (int j = 0; j < 8; ++j) acc[i][j] = 0.0f;

    for (int kt = 0; kt < D_MODEL; kt += 8) {
        float4 a4 = *(const float4*)(Ag + kt);
        float4 b4 = *(const float4*)(Wg + (size_t)kt * N);
        __syncthreads();
        As[acol + 0][arow] = a4.x;
        As[acol + 1][arow] = a4.y;
        As[acol + 2][arow] = a4.z;
        As[acol + 3][arow] = a4.w;
        *(float4*)&Bs[brow][bcol] = b4;
        __syncthreads();

#pragma unroll
        for (int k = 0; k < 8; ++k) {
            float a[8], b[8];
            *(float4*)(a + 0) = *(const float4*)&As[k][ty * 8 + 0];
            *(float4*)(a + 4) = *(const float4*)&As[k][ty * 8 + 4];
            *(float4*)(b + 0) = *(const float4*)&Bs[k][tx * 8 + 0];
            *(float4*)(b + 4) = *(const float4*)&Bs[k][tx * 8 + 4];
#pragma unroll
            for (int i = 0; i < 8; ++i)
#pragma unroll
                for (int j = 0; j < 8; ++j)
                    acc[i][j] = fmaf(a[i], b[j], acc[i][j]);
        }
    }

#pragma unroll
    for (int i = 0; i < 8; ++i) {
        const int row = bm + ty * 8 + i;
        float* Cr = C + (size_t)row * N + bn + tx * 8;
#pragma unroll
        for (int j = 0; j < 8; j += 4) {
            float4 v;
            v.x = acc[i][j + 0] + bias[bn + tx * 8 + j + 0];
            v.y = acc[i][j + 1] + bias[bn + tx * 8 + j + 1];
            v.z = acc[i][j + 2] + bias[bn + tx * 8 + j + 2];
            v.w = acc[i][j + 3] + bias[bn + tx * 8 + j + 3];
            *(float4*)(Cr + j) = v;
        }
    }
}

// ---------------- sampling: softmax + bilinear gather + weighted sum ---------
// one block per (b, q); 256 threads = 8 heads x 32 dims
__global__ void __launch_bounds__(256)
msda_sample(const float* __restrict__ refp) {
    const int bq  = blockIdx.x;            // 0..21759
    const int b   = bq / LEN_Q;
    const int tid = threadIdx.x;
    const int h   = tid >> 5;              // head 0..7
    const int d   = tid & 31;              // dim 0..31

    __shared__ float s_off[256];
    __shared__ float s_attn[128];
    __shared__ float s_ref[8];

    const size_t rowo = (size_t)bq * 256;
    s_off[tid] = g_off[rowo + tid];
    if (tid < 128) s_attn[tid] = g_attn[(size_t)bq * 128 + tid];
    if (tid < 8)   s_ref[tid]  = refp[(size_t)bq * 8 + tid];
    __syncthreads();

    // softmax over 16 (level,point) logits for this head (redundant per lane)
    float w[16];
    float mx = -1e30f;
#pragma unroll
    for (int j = 0; j < 16; ++j) { w[j] = s_attn[h * 16 + j]; mx = fmaxf(mx, w[j]); }
    float sum = 0.0f;
#pragma unroll
    for (int j = 0; j < 16; ++j) { w[j] = __expf(w[j] - mx); sum += w[j]; }
    const float inv = 1.0f / sum;

    const int   dims[4]   = {64, 32, 16, 8};
    const int   starts[4] = {0, 4096, 5120, 5376};
    const float* vbase = g_value + (size_t)b * LEN_IN * 256 + h * 32 + d;

    float acc = 0.0f;
#pragma unroll
    for (int l = 0; l < 4; ++l) {
        const int   S  = dims[l];          // square level: H == W
        const int   st = starts[l];
        const float fs = (float)S;
        const float rx = s_ref[l * 2 + 0];
        const float ry = s_ref[l * 2 + 1];
#pragma unroll
        for (int p = 0; p < 4; ++p) {
            const int oi = ((h * 4 + l) * 4 + p) * 2;
            // loc = ref + off / (W,H); pixel = loc * S - 0.5 (align_corners=False)
            const float x = fmaf(rx, fs, s_off[oi + 0]) - 0.5f;
            const float y = fmaf(ry, fs, s_off[oi + 1]) - 0.5f;
            const float x0f = floorf(x), y0f = floorf(y);
            const int   x0 = (int)x0f, y0 = (int)y0f;
            const float wx = x - x0f,  wy = y - y0f;

            const bool xin0 = (x0 >= 0)     && (x0 < S);
            const bool xin1 = (x0 + 1 >= 0) && (x0 + 1 < S);
            const bool yin0 = (y0 >= 0)     && (y0 < S);
            const bool yin1 = (y0 + 1 >= 0) && (y0 + 1 < S);

            float v00 = 0.f, v10 = 0.f, v01 = 0.f, v11 = 0.f;
            if (yin0) {
                const size_t rb = (size_t)(st + y0 * S) * 256;
                if (xin0) v00 = vbase[rb + (size_t)x0 * 256];
                if (xin1) v10 = vbase[rb + (size_t)(x0 + 1) * 256];
            }
            if (yin1) {
                const size_t rb = (size_t)(st + (y0 + 1) * S) * 256;
                if (xin0) v01 = vbase[rb + (size_t)x0 * 256];
                if (xin1) v11 = vbase[rb + (size_t)(x0 + 1) * 256];
            }
            const float samp = v00 * (1.f - wx) * (1.f - wy)
                             + v10 * wx         * (1.f - wy)
                             + v01 * (1.f - wx) * wy
                             + v11 * wx         * wy;
            acc = fmaf(w[l * 4 + p] * inv, samp, acc);
        }
    }
    g_mid[rowo + tid] = acc;
}

// ---------------- launch -----------------------------------------------------
extern "C" void kernel_launch(void* const* d_in, const int* in_sizes, int n_in,
                              void* d_out, int out_size) {
    const float* query   = (const float*)d_in[0];
    const float* refp    = (const float*)d_in[1];
    const float* in_flat = (const float*)d_in[2];
    // d_in[3] spatial shapes, d_in[4] level starts: static, hardcoded
    const float* W_val  = (const float*)d_in[5];
    const float* b_val  = (const float*)d_in[6];
    const float* W_off  = (const float*)d_in[7];
    const float* b_off  = (const float*)d_in[8];
    const float* W_attn = (const float*)d_in[9];
    const float* b_attn = (const float*)d_in[10];
    const float* W_out  = (const float*)d_in[11];
    const float* b_out  = (const float*)d_in[12];
    float* out = (float*)d_out;

    float *pv, *po, *pa, *pm;
    cudaGetSymbolAddress((void**)&pv, g_value);
    cudaGetSymbolAddress((void**)&po, g_off);
    cudaGetSymbolAddress((void**)&pa, g_attn);
    cudaGetSymbolAddress((void**)&pm, g_mid);

    const dim3 blk(256);
    const dim3 g256(M_TOTAL / 128, 256 / 128);   // 170 x 2
    const dim3 g128(M_TOTAL / 128, 128 / 128);   // 170 x 1

    sgemm_bias<256><<<g256, blk>>>(in_flat, W_val,  b_val,  pv);
    sgemm_bias<256><<<g256, blk>>>(query,   W_off,  b_off,  po);
    sgemm_bias<128><<<g128, blk>>>(query,   W_attn, b_attn, pa);
    msda_sample<<<M_TOTAL, blk>>>(refp);
    sgemm_bias<256><<<g256, blk>>>(pm, W_out, b_out, out);
}

// round 2
// speedup vs baseline: 1.2847x; 1.2847x over previous
#include <cuda_runtime.h>
#include <math.h>

#define D_MODEL   256
#define N_HEADS   8
#define N_LEVELS  4
#define N_POINTS  4
#define HEAD_DIM  32
#define LEN_IN    5440
#define LEN_Q     5440
#define BATCH     4
#define M_TOTAL   (BATCH * LEN_Q)   // 21760 = 170 * 128

typedef unsigned long long u64;

// ---------------- scratch (static device globals; no allocation) -------------
__device__ float g_value[(size_t)M_TOTAL * D_MODEL];
__device__ float g_off  [(size_t)M_TOTAL * 256];
__device__ float g_attn [(size_t)M_TOTAL * 128];
__device__ float g_mid  [(size_t)M_TOTAL * D_MODEL];

// ---------------- f32x2 helpers (Blackwell packed fp32 pipe) -----------------
__device__ __forceinline__ u64 pack2(float lo, float hi) {
    u64 r; asm("mov.b64 %0, {%1, %2};" : "=l"(r) : "f"(lo), "f"(hi)); return r;
}
__device__ __forceinline__ void unpack2(u64 v, float &lo, float &hi) {
    asm("mov.b64 {%0, %1}, %2;" : "=f"(lo), "=f"(hi) : "l"(v));
}
__device__ __forceinline__ void fma2(u64 &d, u64 a, u64 b) {
    asm("fma.rn.f32x2 %0, %1, %2, %0;" : "+l"(d) : "l"(a), "l"(b));
}

// ---------------- fp32 SGEMM (f32x2 inner): C = A[M,256] @ W[256,N] + bias ---
template <int N>
__global__ void __launch_bounds__(256)
sgemm_bias(const float* __restrict__ A, const float* __restrict__ W,
           const float* __restrict__ bias, float* __restrict__ C) {
    __shared__ float As[8][128];
    __shared__ float Bs[8][128];

    const int tid = threadIdx.x;
    const int bm  = blockIdx.x * 128;
    const int bn  = blockIdx.y * 128;
    const int tx  = tid & 15;
    const int ty  = tid >> 4;

    const int arow = tid >> 1;
    const int acol = (tid & 1) * 4;
    const int brow = tid >> 5;
    const int bcol = (tid & 31) * 4;

    const float* Ag = A + (size_t)(bm + arow) * D_MODEL + acol;
    const float* Wg = W + (size_t)brow * N + bn + bcol;

    u64 acc2[8][4];
    const u64 z2 = pack2(0.0f, 0.0f);
#pragma unroll
    for (int i = 0; i < 8; ++i)
#pragma unroll
        for (int j = 0; j < 4; ++j) acc2[i][j] = z2;

    for (int kt = 0; kt < D_MODEL; kt += 8) {
        float4 a4 = *(const float4*)(Ag + kt);
        float4 b4 = *(const float4*)(Wg + (size_t)kt * N);
        __syncthreads();
        As[acol + 0][arow] = a4.x;
        As[acol + 1][arow] = a4.y;
        As[acol + 2][arow] = a4.z;
        As[acol + 3][arow] = a4.w;
        *(float4*)&Bs[brow][bcol] = b4;
        __syncthreads();

#pragma unroll
        for (int k = 0; k < 8; ++k) {
            float a[8];
            *(float4*)(a + 0) = *(const float4*)&As[k][ty * 8 + 0];
            *(float4*)(a + 4) = *(const float4*)&As[k][ty * 8 + 4];
            u64 b2[4];
            {
                ulonglong2 blo = *(const ulonglong2*)&Bs[k][tx * 8 + 0];
                ulonglong2 bhi = *(const ulonglong2*)&Bs[k][tx * 8 + 4];
                b2[0] = blo.x; b2[1] = blo.y; b2[2] = bhi.x; b2[3] = bhi.y;
            }
#pragma unroll
            for (int i = 0; i < 8; ++i) {
                const u64 ad = pack2(a[i], a[i]);
#pragma unroll
                for (int j = 0; j < 4; ++j) fma2(acc2[i][j], ad, b2[j]);
            }
        }
    }

#pragma unroll
    for (int i = 0; i < 8; ++i) {
        const int row = bm + ty * 8 + i;
        float* Cr = C + (size_t)row * N + bn + tx * 8;
        float o[8];
#pragma unroll
        for (int j = 0; j < 4; ++j) unpack2(acc2[i][j], o[2 * j], o[2 * j + 1]);
#pragma unroll
        for (int j = 0; j < 8; j += 4) {
            float4 v;
            v.x = o[j + 0] + bias[bn + tx * 8 + j + 0];
            v.y = o[j + 1] + bias[bn + tx * 8 + j + 1];
            v.z = o[j + 2] + bias[bn + tx * 8 + j + 2];
            v.w = o[j + 3] + bias[bn + tx * 8 + j + 3];
            *(float4*)(Cr + j) = v;
        }
    }
}

// ---------------- sampling: lanes 0-15 precompute, 32 lanes gather -----------
// one block per (b, q); 8 warps = 8 heads; warp lane d = channel dim
__global__ void __launch_bounds__(256)
msda_sample(const float* __restrict__ refp) {
    const int bq   = blockIdx.x;
    const int b    = bq / LEN_Q;
    const int tid  = threadIdx.x;
    const int h    = tid >> 5;
    const int lane = tid & 31;

    __shared__ int   s_idx[8][16][4];
    __shared__ float s_w  [8][16][4];

    const size_t rowo = (size_t)bq * 256;

    // ---- precompute phase: 16 producer lanes per warp (others shadow) ----
    {
        const int ln = lane & 15;           // point id 0..15
        const int l  = ln >> 2;             // level

        // softmax over this head's 16 logits (one logit per producer lane)
        float logit = g_attn[(size_t)bq * 128 + h * 16 + ln];
        float m = logit;
#pragma unroll
        for (int s = 8; s; s >>= 1) m = fmaxf(m, __shfl_xor_sync(0xffffffffu, m, s, 16));
        float e = __expf(logit - m);
        float ssum = e;
#pragma unroll
        for (int s = 8; s; s >>= 1) ssum += __shfl_xor_sync(0xffffffffu, ssum, s, 16);
        const float aw = e / ssum;

        const int S  = 64 >> l;             // 64,32,16,8
        const int st = (l == 0) ? 0 : (l == 1) ? 4096 : (l == 2) ? 5120 : 5376;
        const float fs = (float)S;

        const float rx = refp[(size_t)bq * 8 + l * 2 + 0];
        const float ry = refp[(size_t)bq * 8 + l * 2 + 1];
        const float ox = g_off[rowo + h * 32 + ln * 2 + 0];
        const float oy = g_off[rowo + h * 32 + ln * 2 + 1];

        const float x = fmaf(rx, fs, ox) - 0.5f;
        const float y = fmaf(ry, fs, oy) - 0.5f;
        const float x0f = floorf(x), y0f = floorf(y);
        const int ix0 = (int)x0f, iy0 = (int)y0f;
        const float wx = x - x0f, wy = y - y0f;

        const float fx0 = (unsigned)ix0       < (unsigned)S ? 1.0f : 0.0f;
        const float fx1 = (unsigned)(ix0 + 1) < (unsigned)S ? 1.0f : 0.0f;
        const float fy0 = (unsigned)iy0       < (unsigned)S ? 1.0f : 0.0f;
        const float fy1 = (unsigned)(iy0 + 1) < (unsigned)S ? 1.0f : 0.0f;

        const int cx0 = min(max(ix0, 0), S - 1);
        const int cx1 = min(max(ix0 + 1, 0), S - 1);
        const int cy0 = min(max(iy0, 0), S - 1);
        const int cy1 = min(max(iy0 + 1, 0), S - 1);

        if (lane < 16) {
            s_idx[h][ln][0] = (st + cy0 * S + cx0) * 256;
            s_idx[h][ln][1] = (st + cy0 * S + cx1) * 256;
            s_idx[h][ln][2] = (st + cy1 * S + cx0) * 256;
            s_idx[h][ln][3] = (st + cy1 * S + cx1) * 256;
            s_w[h][ln][0] = aw * (1.0f - wx) * (1.0f - wy) * fx0 * fy0;
            s_w[h][ln][1] = aw * wx          * (1.0f - wy) * fx1 * fy0;
            s_w[h][ln][2] = aw * (1.0f - wx) * wy          * fx0 * fy1;
            s_w[h][ln][3] = aw * wx          * wy          * fx1 * fy1;
        }
    }
    __syncwarp();

    // ---- gather phase: branch-free, 4 independent accumulators ----
    const float* vb = g_value + (size_t)b * (LEN_IN * 256) + h * 32 + lane;
    float a0 = 0.f, a1 = 0.f, a2 = 0.f, a3 = 0.f;
#pragma unroll
    for (int p = 0; p < 16; ++p) {
        const int4   ix = *(const int4*)  s_idx[h][p];
        const float4 cw = *(const float4*) s_w[h][p];
        a0 = fmaf(cw.x, __ldg(vb + ix.x), a0);
        a1 = fmaf(cw.y, __ldg(vb + ix.y), a1);
        a2 = fmaf(cw.z, __ldg(vb + ix.z), a2);
        a3 = fmaf(cw.w, __ldg(vb + ix.w), a3);
    }
    g_mid[rowo + tid] = (a0 + a1) + (a2 + a3);
}

// ---------------- launch -----------------------------------------------------
extern "C" void kernel_launch(void* const* d_in, const int* in_sizes, int n_in,
                              void* d_out, int out_size) {
    const float* query   = (const float*)d_in[0];
    const float* refp    = (const float*)d_in[1];
    const float* in_flat = (const float*)d_in[2];
    const float* W_val  = (const float*)d_in[5];
    const float* b_val  = (const float*)d_in[6];
    const float* W_off  = (const float*)d_in[7];
    const float* b_off  = (const float*)d_in[8];
    const float* W_attn = (const float*)d_in[9];
    const float* b_attn = (const float*)d_in[10];
    const float* W_out  = (const float*)d_in[11];
    const float* b_out  = (const float*)d_in[12];
    float* out = (float*)d_out;

    float *pv, *po, *pa, *pm;
    cudaGetSymbolAddress((void**)&pv, g_value);
    cudaGetSymbolAddress((void**)&po, g_off);
    cudaGetSymbolAddress((void**)&pa, g_attn);
    cudaGetSymbolAddress((void**)&pm, g_mid);

    const dim3 blk(256);
    const dim3 g256(M_TOTAL / 128, 2);
    const dim3 g128(M_TOTAL / 128, 1);

    sgemm_bias<256><<<g256, blk>>>(in_flat, W_val,  b_val,  pv);
    sgemm_bias<256><<<g256, blk>>>(query,   W_off,  b_off,  po);
    sgemm_bias<128><<<g128, blk>>>(query,   W_attn, b_attn, pa);
    msda_sample<<<M_TOTAL, blk>>>(refp);
    sgemm_bias<256><<<g256, blk>>>(pm, W_out, b_out, out);
}

// round 4
// speedup vs baseline: 2.4941x; 1.9414x over previous
#include <cuda_runtime.h>
#include <cstdint>
#include <math.h>

#define D_MODEL   256
#define N_HEADS   8
#define LEN_IN    5440
#define LEN_Q     5440
#define BATCH     4
#define M_TOTAL   (BATCH * LEN_Q)   // 21760 = 170 * 128

// ---------------- scratch (static device globals; no allocation) -------------
__device__ float g_value[(size_t)M_TOTAL * 256];
__device__ float g_off  [(size_t)M_TOTAL * 256];
__device__ float g_attn [(size_t)M_TOTAL * 128];
__device__ float g_mid  [(size_t)M_TOTAL * 256];
// transposed weights [N, K] K-major
__device__ float g_wvT [256 * 256];
__device__ float g_woT [256 * 256];
__device__ float g_waT [128 * 256];
__device__ float g_wouT[256 * 256];

// ---------------- PTX helpers ------------------------------------------------
__device__ __forceinline__ uint32_t smem_u32(const void* p) {
    uint32_t a;
    asm("{ .reg .u64 t; cvta.to.shared.u64 t, %1; cvt.u32.u64 %0, t; }" : "=r"(a) : "l"(p));
    return a;
}
__device__ __forceinline__ void cp_async16(uint32_t dst, const void* src) {
    asm volatile("cp.async.cg.shared.global [%0], [%1], 16;" :: "r"(dst), "l"(src));
}
#define CP_COMMIT() asm volatile("cp.async.commit_group;" ::: "memory")
#define CP_WAIT(n)  asm volatile("cp.async.wait_group %0;" :: "n"(n) : "memory")

__device__ __forceinline__ uint32_t f2tf(float x) {
    uint32_t r; asm("cvt.rna.tf32.f32 %0, %1;" : "=r"(r) : "f"(x)); return r;
}
__device__ __forceinline__ void mma_tf32(float* c, const uint32_t* a, const uint32_t* b) {
    asm volatile("mma.sync.aligned.m16n8k8.row.col.f32.tf32.tf32.f32 "
        "{%0,%1,%2,%3}, {%4,%5,%6,%7}, {%8,%9}, {%0,%1,%2,%3};"
        : "+f"(c[0]), "+f"(c[1]), "+f"(c[2]), "+f"(c[3])
        : "r"(a[0]), "r"(a[1]), "r"(a[2]), "r"(a[3]), "r"(b[0]), "r"(b[1]));
}

// ---------------- weight transpose: Wt[n][k] = W[k][n] -----------------------
__global__ void transpose_w(const float* __restrict__ W, float* __restrict__ Wt,
                            int K, int N) {
    __shared__ float t[32][33];
    const int bx = blockIdx.x * 32;  // n
    const int by = blockIdx.y * 32;  // k
    const int x = threadIdx.x, y = threadIdx.y;
#pragma unroll
    for (int i = 0; i < 32; i += 8) t[y + i][x] = W[(by + y + i) * N + bx + x];
    __syncthreads();
#pragma unroll
    for (int i = 0; i < 32; i += 8) Wt[(bx + y + i) * K + by + x] = t[x][y + i];
}

// ---------------- TF32 tensor-core GEMM --------------------------------------
// C[M,NTOT] = A[M,256] @ Wt[N,256]^T + bias.  CTA tile 128x128, BK=32,
// 8 warps (2m x 4n), warp tile 64x32 via 16x m16n8k8. Double-buffered cp.async.
#define TSTRIDE 36                       // padded floats per smem row
#define TILE_F  (128 * TSTRIDE)          // floats per tile
#define BUF_F   (2 * TILE_F)             // A+B per buffer
#define SMEM_F  (2 * BUF_F)              // double buffered
#define SMEM_B  (SMEM_F * 4)

template <int NTOT>
__global__ void __launch_bounds__(256)
gemm_tc(const float* __restrict__ A, const float* __restrict__ Wt,
        const float* __restrict__ bias, float* __restrict__ C) {
    extern __shared__ float sm[];
    const int tid  = threadIdx.x;
    const int wid  = tid >> 5;
    const int lane = tid & 31;
    const int gid  = lane >> 2;     // 0..7
    const int tg   = lane & 3;      // 0..3
    const int bm   = blockIdx.x * 128;
    const int bn   = blockIdx.y * 128;
    const int mbase = (wid >> 2) * 64;
    const int nbase = (wid & 3) * 32;

    const float* Ab = A  + (size_t)bm * 256;
    const float* Bb = Wt + (size_t)bn * 256;
    const uint32_t smb = smem_u32(sm);

    // per-thread load slots: idx = tid + i*256 -> row idx>>3, float4-col idx&7
    const int lrow = tid >> 3;          // base row (stride 32 across i)
    const int lcol = (tid & 7) * 4;

    auto load_tile = [&](int buf, int kc) {
        const uint32_t dA = smb + (uint32_t)(buf * BUF_F) * 4;
        const uint32_t dB = dA + (uint32_t)TILE_F * 4;
#pragma unroll
        for (int i = 0; i < 4; ++i) {
            const int r = lrow + i * 32;
            const uint32_t off = (uint32_t)(r * TSTRIDE + lcol) * 4;
            cp_async16(dA + off, Ab + (size_t)r * 256 + kc + lcol);
            cp_async16(dB + off, Bb + (size_t)r * 256 + kc + lcol);
        }
        CP_COMMIT();
    };

    float acc[4][4][4];
#pragma unroll
    for (int mt = 0; mt < 4; ++mt)
#pragma unroll
        for (int nt = 0; nt < 4; ++nt)
#pragma unroll
            for (int i = 0; i < 4; ++i) acc[mt][nt][i] = 0.0f;

    load_tile(0, 0);
#pragma unroll 1
    for (int c = 0; c < 8; ++c) {
        if (c < 7) { load_tile((c + 1) & 1, (c + 1) * 32); CP_WAIT(1); }
        else       { CP_WAIT(0); }
        __syncthreads();

        const float* As = sm + (c & 1) * BUF_F;
        const float* Bs = As + TILE_F;
#pragma unroll
        for (int k8 = 0; k8 < 4; ++k8) {
            const int kk = k8 * 8;
            uint32_t bf[4][2];
#pragma unroll
            for (int nt = 0; nt < 4; ++nt) {
                const int nr = nbase + nt * 8 + gid;
                bf[nt][0] = f2tf(Bs[nr * TSTRIDE + kk + tg]);
                bf[nt][1] = f2tf(Bs[nr * TSTRIDE + kk + tg + 4]);
            }
            uint32_t af[4][4];
#pragma unroll
            for (int mt = 0; mt < 4; ++mt) {
                const int r0 = mbase + mt * 16 + gid;
                af[mt][0] = f2tf(As[r0 * TSTRIDE + kk + tg]);
                af[mt][1] = f2tf(As[(r0 + 8) * TSTRIDE + kk + tg]);
                af[mt][2] = f2tf(As[r0 * TSTRIDE + kk + tg + 4]);
                af[mt][3] = f2tf(As[(r0 + 8) * TSTRIDE + kk + tg + 4]);
            }
#pragma unroll
            for (int mt = 0; mt < 4; ++mt)
#pragma unroll
                for (int nt = 0; nt < 4; ++nt)
                    mma_tf32(acc[mt][nt], af[mt], bf[nt]);
        }
        __syncthreads();
    }

    // epilogue: c0,c1 -> (row0, col..col+1); c2,c3 -> (row0+8, ...)
#pragma unroll
    for (int mt = 0; mt < 4; ++mt) {
        const int row0 = bm + mbase + mt * 16 + gid;
#pragma unroll
        for (int nt = 0; nt < 4; ++nt) {
            const int col = bn + nbase + nt * 8 + tg * 2;
            const float2 bv = *(const float2*)(bias + col);
            float2 v0, v1;
            v0.x = acc[mt][nt][0] + bv.x;  v0.y = acc[mt][nt][1] + bv.y;
            v1.x = acc[mt][nt][2] + bv.x;  v1.y = acc[mt][nt][3] + bv.y;
            *(float2*)(C + (size_t)row0 * NTOT + col)       = v0;
            *(float2*)(C + (size_t)(row0 + 8) * NTOT + col) = v1;
        }
    }
}

// ---------------- sampling: lanes 0-15 precompute, 32 lanes gather -----------
__global__ void __launch_bounds__(256)
msda_sample(const float* __restrict__ refp) {
    const int bq   = blockIdx.x;
    const int b    = bq / LEN_Q;
    const int tid  = threadIdx.x;
    const int h    = tid >> 5;
    const int lane = tid & 31;

    __shared__ int   s_idx[8][16][4];
    __shared__ float s_w  [8][16][4];

    const size_t rowo = (size_t)bq * 256;

    {
        const int ln = lane & 15;
        const int l  = ln >> 2;

        float logit = g_attn[(size_t)bq * 128 + h * 16 + ln];
        float m = logit;
#pragma unroll
        for (int s = 8; s; s >>= 1) m = fmaxf(m, __shfl_xor_sync(0xffffffffu, m, s, 16));
        float e = __expf(logit - m);
        float ssum = e;
#pragma unroll
        for (int s = 8; s; s >>= 1) ssum += __shfl_xor_sync(0xffffffffu, ssum, s, 16);
        const float aw = e / ssum;

        const int S  = 64 >> l;
        const int st = (l == 0) ? 0 : (l == 1) ? 4096 : (l == 2) ? 5120 : 5376;
        const float fs = (float)S;

        const float rx = refp[(size_t)bq * 8 + l * 2 + 0];
        const float ry = refp[(size_t)bq * 8 + l * 2 + 1];
        const float ox = g_off[rowo + h * 32 + ln * 2 + 0];
        const float oy = g_off[rowo + h * 32 + ln * 2 + 1];

        const float x = fmaf(rx, fs, ox) - 0.5f;
        const float y = fmaf(ry, fs, oy) - 0.5f;
        const float x0f = floorf(x), y0f = floorf(y);
        const int ix0 = (int)x0f, iy0 = (int)y0f;
        const float wx = x - x0f, wy = y - y0f;

        const float fx0 = (unsigned)ix0       < (unsigned)S ? 1.0f : 0.0f;
        const float fx1 = (unsigned)(ix0 + 1) < (unsigned)S ? 1.0f : 0.0f;
        const float fy0 = (unsigned)iy0       < (unsigned)S ? 1.0f : 0.0f;
        const float fy1 = (unsigned)(iy0 + 1) < (unsigned)S ? 1.0f : 0.0f;

        const int cx0 = min(max(ix0, 0), S - 1);
        const int cx1 = min(max(ix0 + 1, 0), S - 1);
        const int cy0 = min(max(iy0, 0), S - 1);
        const int cy1 = min(max(iy0 + 1, 0), S - 1);

        if (lane < 16) {
            s_idx[h][ln][0] = (st + cy0 * S + cx0) * 256;
            s_idx[h][ln][1] = (st + cy0 * S + cx1) * 256;
            s_idx[h][ln][2] = (st + cy1 * S + cx0) * 256;
            s_idx[h][ln][3] = (st + cy1 * S + cx1) * 256;
            s_w[h][ln][0] = aw * (1.0f - wx) * (1.0f - wy) * fx0 * fy0;
            s_w[h][ln][1] = aw * wx          * (1.0f - wy) * fx1 * fy0;
            s_w[h][ln][2] = aw * (1.0f - wx) * wy          * fx0 * fy1;
            s_w[h][ln][3] = aw * wx          * wy          * fx1 * fy1;
        }
    }
    __syncwarp();

    const float* vb = g_value + (size_t)b * (LEN_IN * 256) + h * 32 + lane;
    float a0 = 0.f, a1 = 0.f, a2 = 0.f, a3 = 0.f;
#pragma unroll
    for (int p = 0; p < 16; ++p) {
        const int4   ix = *(const int4*)  s_idx[h][p];
        const float4 cw = *(const float4*) s_w[h][p];
        a0 = fmaf(cw.x, __ldg(vb + ix.x), a0);
        a1 = fmaf(cw.y, __ldg(vb + ix.y), a1);
        a2 = fmaf(cw.z, __ldg(vb + ix.z), a2);
        a3 = fmaf(cw.w, __ldg(vb + ix.w), a3);
    }
    g_mid[rowo + tid] = (a0 + a1) + (a2 + a3);
}

// ---------------- launch -----------------------------------------------------
extern "C" void kernel_launch(void* const* d_in, const int* in_sizes, int n_in,
                              void* d_out, int out_size) {
    const float* query   = (const float*)d_in[0];
    const float* refp    = (const float*)d_in[1];
    const float* in_flat = (const float*)d_in[2];
    const float* W_val  = (const float*)d_in[5];
    const float* b_val  = (const float*)d_in[6];
    const float* W_off  = (const float*)d_in[7];
    const float* b_off  = (const float*)d_in[8];
    const float* W_attn = (const float*)d_in[9];
    const float* b_attn = (const float*)d_in[10];
    const float* W_out  = (const float*)d_in[11];
    const float* b_out  = (const float*)d_in[12];
    float* out = (float*)d_out;

    float *pv, *po, *pa, *pm, *wvT, *woT, *waT, *wouT;
    cudaGetSymbolAddress((void**)&pv,  g_value);
    cudaGetSymbolAddress((void**)&po,  g_off);
    cudaGetSymbolAddress((void**)&pa,  g_attn);
    cudaGetSymbolAddress((void**)&pm,  g_mid);
    cudaGetSymbolAddress((void**)&wvT, g_wvT);
    cudaGetSymbolAddress((void**)&woT, g_woT);
    cudaGetSymbolAddress((void**)&waT, g_waT);
    cudaGetSymbolAddress((void**)&wouT, g_wouT);

    cudaFuncSetAttribute(gemm_tc<256>, cudaFuncAttributeMaxDynamicSharedMemorySize, SMEM_B);
    cudaFuncSetAttribute(gemm_tc<128>, cudaFuncAttributeMaxDynamicSharedMemorySize, SMEM_B);

    const dim3 tb(32, 8);
    transpose_w<<<dim3(8, 8), tb>>>(W_val,  wvT,  256, 256);
    transpose_w<<<dim3(8, 8), tb>>>(W_off,  woT,  256, 256);
    transpose_w<<<dim3(4, 8), tb>>>(W_attn, waT,  256, 128);
    transpose_w<<<dim3(8, 8), tb>>>(W_out,  wouT, 256, 256);

    gemm_tc<256><<<dim3(M_TOTAL / 128, 2), 256, SMEM_B>>>(in_flat, wvT, b_val, pv);
    gemm_tc<256><<<dim3(M_TOTAL / 128, 2), 256, SMEM_B>>>(query,   woT, b_off, po);
    gemm_tc<128><<<dim3(M_TOTAL / 128, 1), 256, SMEM_B>>>(query,   waT, b_attn, pa);
    msda_sample<<<M_TOTAL, 256>>>(refp);
    gemm_tc<256><<<dim3(M_TOTAL / 128, 2), 256, SMEM_B>>>(pm, wouT, b_out, out);
}

// round 5
// speedup vs baseline: 2.9498x; 1.1827x over previous
#include <cuda_runtime.h>
#include <cstdint>
#include <math.h>

#define D_MODEL   256
#define N_HEADS   8
#define LEN_IN    5440
#define LEN_Q     5440
#define BATCH     4
#define M_TOTAL   (BATCH * LEN_Q)   // 21760 = 170 * 128

// ---------------- scratch (static device globals; no allocation) -------------
__device__ float g_value[(size_t)M_TOTAL * 256];
__device__ float g_off  [(size_t)M_TOTAL * 256];
__device__ float g_attn [(size_t)M_TOTAL * 128];
__device__ float g_mid  [(size_t)M_TOTAL * 256];
// transposed + tf32-pre-rounded weights [N, K] K-major
__device__ float g_wvT [256 * 256];
__device__ float g_woT [256 * 256];
__device__ float g_waT [128 * 256];
__device__ float g_wouT[256 * 256];

// ---------------- PTX helpers ------------------------------------------------
__device__ __forceinline__ uint32_t smem_u32(const void* p) {
    uint32_t a;
    asm("{ .reg .u64 t; cvta.to.shared.u64 t, %1; cvt.u32.u64 %0, t; }" : "=r"(a) : "l"(p));
    return a;
}
__device__ __forceinline__ void cp_async16(uint32_t dst, const void* src) {
    asm volatile("cp.async.cg.shared.global [%0], [%1], 16;" :: "r"(dst), "l"(src));
}
#define CP_COMMIT() asm volatile("cp.async.commit_group;" ::: "memory")
#define CP_WAIT(n)  asm volatile("cp.async.wait_group %0;" :: "n"(n) : "memory")

__device__ __forceinline__ uint32_t f2tf(float x) {
    uint32_t r; asm("cvt.rna.tf32.f32 %0, %1;" : "=r"(r) : "f"(x)); return r;
}
__device__ __forceinline__ void mma_tf32(float* c, const uint32_t* a, const uint32_t* b) {
    asm volatile("mma.sync.aligned.m16n8k8.row.col.f32.tf32.tf32.f32 "
        "{%0,%1,%2,%3}, {%4,%5,%6,%7}, {%8,%9}, {%0,%1,%2,%3};"
        : "+f"(c[0]), "+f"(c[1]), "+f"(c[2]), "+f"(c[3])
        : "r"(a[0]), "r"(a[1]), "r"(a[2]), "r"(a[3]), "r"(b[0]), "r"(b[1]));
}

// ---------------- fused weight transpose + tf32 pre-round --------------------
// grid.x = 64 tiles (8 n-tiles x 8 k-tiles), grid.y = matrix id 0..3
__global__ void transpose_all(const float* __restrict__ Wv, const float* __restrict__ Wo,
                              const float* __restrict__ Wa, const float* __restrict__ Wou,
                              float* __restrict__ WvT, float* __restrict__ WoT,
                              float* __restrict__ WaT, float* __restrict__ WouT) {
    __shared__ float t[32][33];
    const int m = blockIdx.y;
    const float* W; float* Wt; int N;
    if      (m == 0) { W = Wv;  Wt = WvT;  N = 256; }
    else if (m == 1) { W = Wo;  Wt = WoT;  N = 256; }
    else if (m == 2) { W = Wa;  Wt = WaT;  N = 128; }
    else             { W = Wou; Wt = WouT; N = 256; }
    const int bx = (blockIdx.x & 7) * 32;   // n
    const int by = (blockIdx.x >> 3) * 32;  // k
    if (bx >= N) return;
    const int x = threadIdx.x, y = threadIdx.y;
#pragma unroll
    for (int i = 0; i < 32; i += 8) t[y + i][x] = W[(by + y + i) * N + bx + x];
    __syncthreads();
#pragma unroll
    for (int i = 0; i < 32; i += 8)
        Wt[(bx + y + i) * 256 + by + x] = __uint_as_float(f2tf(t[x][y + i]));
}

// ---------------- TF32 tensor-core GEMM --------------------------------------
// CTA tile 128x128, BK=32, 8 warps (2m x 4n), warp tile 64x32 (16x m16n8k8),
// double-buffered cp.async. B (weights) pre-rounded to tf32 -> raw bits.
// mode 0: grid.y 0..4 = {value n0,n1 | off n0,n1 | attn}.  mode 1: out proj.
#define TSTRIDE 36
#define TILE_F  (128 * TSTRIDE)
#define BUF_F   (2 * TILE_F)
#define SMEM_B  (2 * BUF_F * 4)

__global__ void __launch_bounds__(256, 2)
gemm_tc(const float* __restrict__ A0, const float* __restrict__ A1,
        const float* __restrict__ W0, const float* __restrict__ W1, const float* __restrict__ W2,
        const float* __restrict__ b0, const float* __restrict__ b1, const float* __restrict__ b2,
        float* __restrict__ C0, float* __restrict__ C1, float* __restrict__ C2,
        int mode) {
    extern __shared__ float sm[];
    const int tid  = threadIdx.x;
    const int wid  = tid >> 5;
    const int lane = tid & 31;
    const int gid  = lane >> 2;
    const int tg   = lane & 3;
    const int bm   = blockIdx.x * 128;
    const int mbase = (wid >> 2) * 64;
    const int nbase = (wid & 3) * 32;

    const float *A, *Wt, *bias; float* C; int NTOT = 256; int bn;
    {
        const int y = blockIdx.y;
        if (mode == 0) {
            if (y < 2)      { A = A0; Wt = W0; bias = b0; C = C0; bn = y * 128; }
            else if (y < 4) { A = A1; Wt = W1; bias = b1; C = C1; bn = (y - 2) * 128; }
            else            { A = A1; Wt = W2; bias = b2; C = C2; bn = 0; NTOT = 128; }
        } else              { A = A0; Wt = W0; bias = b0; C = C0; bn = y * 128; }
    }

    const float* Ab = A  + (size_t)bm * 256;
    const float* Bb = Wt + (size_t)bn * 256;
    const uint32_t smb = smem_u32(sm);

    const int lrow = tid >> 3;
    const int lcol = (tid & 7) * 4;

    auto load_tile = [&](int buf, int kc) {
        const uint32_t dA = smb + (uint32_t)(buf * BUF_F) * 4;
        const uint32_t dB = dA + (uint32_t)TILE_F * 4;
#pragma unroll
        for (int i = 0; i < 4; ++i) {
            const int r = lrow + i * 32;
            const uint32_t off = (uint32_t)(r * TSTRIDE + lcol) * 4;
            cp_async16(dA + off, Ab + (size_t)r * 256 + kc + lcol);
            cp_async16(dB + off, Bb + (size_t)r * 256 + kc + lcol);
        }
        CP_COMMIT();
    };

    float acc[4][4][4];
#pragma unroll
    for (int mt = 0; mt < 4; ++mt)
#pragma unroll
        for (int nt = 0; nt < 4; ++nt)
#pragma unroll
            for (int i = 0; i < 4; ++i) acc[mt][nt][i] = 0.0f;

    load_tile(0, 0);
#pragma unroll 1
    for (int c = 0; c < 8; ++c) {
        if (c < 7) { load_tile((c + 1) & 1, (c + 1) * 32); CP_WAIT(1); }
        else       { CP_WAIT(0); }
        __syncthreads();

        const float* As = sm + (c & 1) * BUF_F;
        const float* Bs = As + TILE_F;
#pragma unroll
        for (int k8 = 0; k8 < 4; ++k8) {
            const int kk = k8 * 8;
            uint32_t bf[4][2];
#pragma unroll
            for (int nt = 0; nt < 4; ++nt) {
                const int nr = nbase + nt * 8 + gid;
                bf[nt][0] = __float_as_uint(Bs[nr * TSTRIDE + kk + tg]);      // pre-rounded
                bf[nt][1] = __float_as_uint(Bs[nr * TSTRIDE + kk + tg + 4]);
            }
            uint32_t af[4][4];
#pragma unroll
            for (int mt = 0; mt < 4; ++mt) {
                const int r0 = mbase + mt * 16 + gid;
                af[mt][0] = f2tf(As[r0 * TSTRIDE + kk + tg]);
                af[mt][1] = f2tf(As[(r0 + 8) * TSTRIDE + kk + tg]);
                af[mt][2] = f2tf(As[r0 * TSTRIDE + kk + tg + 4]);
                af[mt][3] = f2tf(As[(r0 + 8) * TSTRIDE + kk + tg + 4]);
            }
#pragma unroll
            for (int mt = 0; mt < 4; ++mt)
#pragma unroll
                for (int nt = 0; nt < 4; ++nt)
                    mma_tf32(acc[mt][nt], af[mt], bf[nt]);
        }
        __syncthreads();
    }

#pragma unroll
    for (int mt = 0; mt < 4; ++mt) {
        const int row0 = bm + mbase + mt * 16 + gid;
#pragma unroll
        for (int nt = 0; nt < 4; ++nt) {
            const int col = bn + nbase + nt * 8 + tg * 2;
            const float2 bv = *(const float2*)(bias + col);
            float2 v0, v1;
            v0.x = acc[mt][nt][0] + bv.x;  v0.y = acc[mt][nt][1] + bv.y;
            v1.x = acc[mt][nt][2] + bv.x;  v1.y = acc[mt][nt][3] + bv.y;
            *(float2*)(C + (size_t)row0 * NTOT + col)       = v0;
            *(float2*)(C + (size_t)(row0 + 8) * NTOT + col) = v1;
        }
    }
}

// ---------------- sampling: lanes 0-15 precompute, 32 lanes gather -----------
__global__ void __launch_bounds__(256)
msda_sample(const float* __restrict__ refp) {
    const int bq   = blockIdx.x;
    const int b    = bq / LEN_Q;
    const int tid  = threadIdx.x;
    const int h    = tid >> 5;
    const int lane = tid & 31;

    __shared__ int   s_idx[8][16][4];
    __shared__ float s_w  [8][16][4];

    const size_t rowo = (size_t)bq * 256;

    {
        const int ln = lane & 15;
        const int l  = ln >> 2;

        float logit = g_attn[(size_t)bq * 128 + h * 16 + ln];
        float m = logit;
#pragma unroll
        for (int s = 8; s; s >>= 1) m = fmaxf(m, __shfl_xor_sync(0xffffffffu, m, s, 16));
        float e = __expf(logit - m);
        float ssum = e;
#pragma unroll
        for (int s = 8; s; s >>= 1) ssum += __shfl_xor_sync(0xffffffffu, ssum, s, 16);
        const float aw = e / ssum;

        const int S  = 64 >> l;
        const int st = (l == 0) ? 0 : (l == 1) ? 4096 : (l == 2) ? 5120 : 5376;
        const float fs = (float)S;

        const float rx = refp[(size_t)bq * 8 + l * 2 + 0];
        const float ry = refp[(size_t)bq * 8 + l * 2 + 1];
        const float ox = g_off[rowo + h * 32 + ln * 2 + 0];
        const float oy = g_off[rowo + h * 32 + ln * 2 + 1];

        const float x = fmaf(rx, fs, ox) - 0.5f;
        const float y = fmaf(ry, fs, oy) - 0.5f;
        const float x0f = floorf(x), y0f = floorf(y);
        const int ix0 = (int)x0f, iy0 = (int)y0f;
        const float wx = x - x0f, wy = y - y0f;

        const float fx0 = (unsigned)ix0       < (unsigned)S ? 1.0f : 0.0f;
        const float fx1 = (unsigned)(ix0 + 1) < (unsigned)S ? 1.0f : 0.0f;
        const float fy0 = (unsigned)iy0       < (unsigned)S ? 1.0f : 0.0f;
        const float fy1 = (unsigned)(iy0 + 1) < (unsigned)S ? 1.0f : 0.0f;

        const int cx0 = min(max(ix0, 0), S - 1);
        const int cx1 = min(max(ix0 + 1, 0), S - 1);
        const int cy0 = min(max(iy0, 0), S - 1);
        const int cy1 = min(max(iy0 + 1, 0), S - 1);

        if (lane < 16) {
            s_idx[h][ln][0] = (st + cy0 * S + cx0) * 256;
            s_idx[h][ln][1] = (st + cy0 * S + cx1) * 256;
            s_idx[h][ln][2] = (st + cy1 * S + cx0) * 256;
            s_idx[h][ln][3] = (st + cy1 * S + cx1) * 256;
            s_w[h][ln][0] = aw * (1.0f - wx) * (1.0f - wy) * fx0 * fy0;
            s_w[h][ln][1] = aw * wx          * (1.0f - wy) * fx1 * fy0;
            s_w[h][ln][2] = aw * (1.0f - wx) * wy          * fx0 * fy1;
            s_w[h][ln][3] = aw * wx          * wy          * fx1 * fy1;
        }
    }
    __syncwarp();

    const float* vb = g_value + (size_t)b * (LEN_IN * 256) + h * 32 + lane;
    float a0 = 0.f, a1 = 0.f, a2 = 0.f, a3 = 0.f;
#pragma unroll
    for (int p = 0; p < 16; ++p) {
        const int4   ix = *(const int4*)  s_idx[h][p];
        const float4 cw = *(const float4*) s_w[h][p];
        a0 = fmaf(cw.x, __ldg(vb + ix.x), a0);
        a1 = fmaf(cw.y, __ldg(vb + ix.y), a1);
        a2 = fmaf(cw.z, __ldg(vb + ix.z), a2);
        a3 = fmaf(cw.w, __ldg(vb + ix.w), a3);
    }
    g_mid[rowo + tid] = (a0 + a1) + (a2 + a3);
}

// ---------------- launch -----------------------------------------------------
extern "C" void kernel_launch(void* const* d_in, const int* in_sizes, int n_in,
                              void* d_out, int out_size) {
    const float* query   = (const float*)d_in[0];
    const float* refp    = (const float*)d_in[1];
    const float* in_flat = (const float*)d_in[2];
    const float* W_val  = (const float*)d_in[5];
    const float* b_val  = (const float*)d_in[6];
    const float* W_off  = (const float*)d_in[7];
    const float* b_off  = (const float*)d_in[8];
    const float* W_attn = (const float*)d_in[9];
    const float* b_attn = (const float*)d_in[10];
    const float* W_out  = (const float*)d_in[11];
    const float* b_out  = (const float*)d_in[12];
    float* out = (float*)d_out;

    float *pv, *po, *pa, *pm, *wvT, *woT, *waT, *wouT;
    cudaGetSymbolAddress((void**)&pv,  g_value);
    cudaGetSymbolAddress((void**)&po,  g_off);
    cudaGetSymbolAddress((void**)&pa,  g_attn);
    cudaGetSymbolAddress((void**)&pm,  g_mid);
    cudaGetSymbolAddress((void**)&wvT, g_wvT);
    cudaGetSymbolAddress((void**)&woT, g_woT);
    cudaGetSymbolAddress((void**)&waT, g_waT);
    cudaGetSymbolAddress((void**)&wouT, g_wouT);

    cudaFuncSetAttribute(gemm_tc, cudaFuncAttributeMaxDynamicSharedMemorySize, SMEM_B);

    transpose_all<<<dim3(64, 4), dim3(32, 8)>>>(W_val, W_off, W_attn, W_out,
                                                wvT, woT, waT, wouT);

    // fused front GEMMs: value (y=0,1), offsets (y=2,3), attn (y=4)
    gemm_tc<<<dim3(M_TOTAL / 128, 5), 256, SMEM_B>>>(
        in_flat, query, wvT, woT, waT, b_val, b_off, b_attn, pv, po, pa, 0);

    msda_sample<<<M_TOTAL, 256>>>(refp);

    // output projection
    gemm_tc<<<dim3(M_TOTAL / 128, 2), 256, SMEM_B>>>(
        pm, nullptr, wouT, nullptr, nullptr, b_out, nullptr, nullptr,
        out, nullptr, nullptr, 1);
}

// round 6
// speedup vs baseline: 3.1587x; 1.0708x over previous
#include <cuda_runtime.h>
#include <cstdint>
#include <math.h>

#define D_MODEL   256
#define N_HEADS   8
#define LEN_IN    5440
#define LEN_Q     5440
#define BATCH     4
#define M_TOTAL   (BATCH * LEN_Q)   // 21760 = 170 * 128

// k-permutation within groups of 8: pos(k) = [0,4,1,5,2,6,3,7]^-1 mapping
__host__ __device__ __forceinline__ int kperm(int k) {
    return (k & ~7) | ((k & 3) << 1) | ((k >> 2) & 1);
}

// ---------------- scratch (static device globals; no allocation) -------------
__device__ float g_value[(size_t)M_TOTAL * 256];
__device__ float g_off  [(size_t)M_TOTAL * 256];
__device__ float g_attn [(size_t)M_TOTAL * 128];
__device__ float g_mid  [(size_t)M_TOTAL * 256];   // k-permuted + tf32 pre-rounded
// transposed weights [N, K=256] K-major, k-permuted + tf32 pre-rounded
__device__ float g_wvT [256 * 256];
__device__ float g_woT [256 * 256];
__device__ float g_waT [128 * 256];
__device__ float g_wouT[256 * 256];

// ---------------- PTX helpers ------------------------------------------------
__device__ __forceinline__ uint32_t smem_u32(const void* p) {
    uint32_t a;
    asm("{ .reg .u64 t; cvta.to.shared.u64 t, %1; cvt.u32.u64 %0, t; }" : "=r"(a) : "l"(p));
    return a;
}
__device__ __forceinline__ void cp_async16(uint32_t dst, const void* src) {
    asm volatile("cp.async.cg.shared.global [%0], [%1], 16;" :: "r"(dst), "l"(src));
}
#define CP_COMMIT() asm volatile("cp.async.commit_group;" ::: "memory")
#define CP_WAIT(n)  asm volatile("cp.async.wait_group %0;" :: "n"(n) : "memory")

__device__ __forceinline__ uint32_t f2tf(float x) {
    uint32_t r; asm("cvt.rna.tf32.f32 %0, %1;" : "=r"(r) : "f"(x)); return r;
}
__device__ __forceinline__ void mma_tf32(float* c, const uint32_t* a, const uint32_t* b) {
    asm volatile("mma.sync.aligned.m16n8k8.row.col.f32.tf32.tf32.f32 "
        "{%0,%1,%2,%3}, {%4,%5,%6,%7}, {%8,%9}, {%0,%1,%2,%3};"
        : "+f"(c[0]), "+f"(c[1]), "+f"(c[2]), "+f"(c[3])
        : "r"(a[0]), "r"(a[1]), "r"(a[2]), "r"(a[3]), "r"(b[0]), "r"(b[1]));
}

// ------ fused weight transpose + tf32 pre-round + k-permute ------------------
__global__ void transpose_all(const float* __restrict__ Wv, const float* __restrict__ Wo,
                              const float* __restrict__ Wa, const float* __restrict__ Wou,
                              float* __restrict__ WvT, float* __restrict__ WoT,
                              float* __restrict__ WaT, float* __restrict__ WouT) {
    __shared__ float t[32][33];
    const int m = blockIdx.y;
    const float* W; float* Wt; int N;
    if      (m == 0) { W = Wv;  Wt = WvT;  N = 256; }
    else if (m == 1) { W = Wo;  Wt = WoT;  N = 256; }
    else if (m == 2) { W = Wa;  Wt = WaT;  N = 128; }
    else             { W = Wou; Wt = WouT; N = 256; }
    const int bx = (blockIdx.x & 7) * 32;   // n
    const int by = (blockIdx.x >> 3) * 32;  // k
    if (bx >= N) return;
    const int x = threadIdx.x, y = threadIdx.y;
#pragma unroll
    for (int i = 0; i < 32; i += 8) t[y + i][x] = W[(by + y + i) * N + bx + x];
    __syncthreads();
#pragma unroll
    for (int i = 0; i < 32; i += 8)
        Wt[(bx + y + i) * 256 + kperm(by + x)] = __uint_as_float(f2tf(t[x][y + i]));
}

// ---------------- TF32 tensor-core GEMM --------------------------------------
// CTA tile 128x128, BK=32, 8 warps (2m x 4n), warp tile 64x32 (16x m16n8k8).
// B always k-permuted+pre-rounded (float2 raw loads). PRE_A: A too (out-proj).
#define TSTRIDE 36
#define TILE_F  (128 * TSTRIDE)
#define BUF_F   (2 * TILE_F)
#define SMEM_B  (2 * BUF_F * 4)

template <bool PRE_A>
__global__ void __launch_bounds__(256, 2)
gemm_tc(const float* __restrict__ A0, const float* __restrict__ A1,
        const float* __restrict__ W0, const float* __restrict__ W1, const float* __restrict__ W2,
        const float* __restrict__ b0, const float* __restrict__ b1, const float* __restrict__ b2,
        float* __restrict__ C0, float* __restrict__ C1, float* __restrict__ C2) {
    extern __shared__ float sm[];
    const int tid  = threadIdx.x;
    const int wid  = tid >> 5;
    const int lane = tid & 31;
    const int gid  = lane >> 2;
    const int tg   = lane & 3;
    const int bm   = blockIdx.x * 128;
    const int mbase = (wid >> 2) * 64;
    const int nbase = (wid & 3) * 32;

    const float *A, *Wt, *bias; float* C; int NTOT = 256; int bn;
    {
        const int y = blockIdx.y;
        if (!PRE_A) {
            if (y < 2)      { A = A0; Wt = W0; bias = b0; C = C0; bn = y * 128; }
            else if (y < 4) { A = A1; Wt = W1; bias = b1; C = C1; bn = (y - 2) * 128; }
            else            { A = A1; Wt = W2; bias = b2; C = C2; bn = 0; NTOT = 128; }
        } else              { A = A0; Wt = W0; bias = b0; C = C0; bn = y * 128; }
    }

    const float* Ab = A  + (size_t)bm * 256;
    const float* Bb = Wt + (size_t)bn * 256;
    const uint32_t smb = smem_u32(sm);

    const int lrow = tid >> 3;
    const int lcol = (tid & 7) * 4;

    auto load_tile = [&](int buf, int kc) {
        const uint32_t dA = smb + (uint32_t)(buf * BUF_F) * 4;
        const uint32_t dB = dA + (uint32_t)TILE_F * 4;
#pragma unroll
        for (int i = 0; i < 4; ++i) {
            const int r = lrow + i * 32;
            const uint32_t off = (uint32_t)(r * TSTRIDE + lcol) * 4;
            cp_async16(dA + off, Ab + (size_t)r * 256 + kc + lcol);
            cp_async16(dB + off, Bb + (size_t)r * 256 + kc + lcol);
        }
        CP_COMMIT();
    };

    float acc[4][4][4];
#pragma unroll
    for (int mt = 0; mt < 4; ++mt)
#pragma unroll
        for (int nt = 0; nt < 4; ++nt)
#pragma unroll
            for (int i = 0; i < 4; ++i) acc[mt][nt][i] = 0.0f;

    load_tile(0, 0);
#pragma unroll 1
    for (int c = 0; c < 8; ++c) {
        if (c < 7) { load_tile((c + 1) & 1, (c + 1) * 32); CP_WAIT(1); }
        else       { CP_WAIT(0); }
        __syncthreads();

        const float* As = sm + (c & 1) * BUF_F;
        const float* Bs = As + TILE_F;
#pragma unroll
        for (int k8 = 0; k8 < 4; ++k8) {
            const int kk = k8 * 8;
            uint32_t bf[4][2];
#pragma unroll
            for (int nt = 0; nt < 4; ++nt) {
                const int nr = nbase + nt * 8 + gid;
                const float2 b2 = *(const float2*)&Bs[nr * TSTRIDE + kk + 2 * tg];
                bf[nt][0] = __float_as_uint(b2.x);
                bf[nt][1] = __float_as_uint(b2.y);
            }
            uint32_t af[4][4];
#pragma unroll
            for (int mt = 0; mt < 4; ++mt) {
                const int r0 = mbase + mt * 16 + gid;
                if (PRE_A) {
                    const float2 alo = *(const float2*)&As[r0 * TSTRIDE + kk + 2 * tg];
                    const float2 ahi = *(const float2*)&As[(r0 + 8) * TSTRIDE + kk + 2 * tg];
                    af[mt][0] = __float_as_uint(alo.x);
                    af[mt][1] = __float_as_uint(ahi.x);
                    af[mt][2] = __float_as_uint(alo.y);
                    af[mt][3] = __float_as_uint(ahi.y);
                } else {
                    af[mt][0] = f2tf(As[r0 * TSTRIDE + kk + tg]);
                    af[mt][1] = f2tf(As[(r0 + 8) * TSTRIDE + kk + tg]);
                    af[mt][2] = f2tf(As[r0 * TSTRIDE + kk + tg + 4]);
                    af[mt][3] = f2tf(As[(r0 + 8) * TSTRIDE + kk + tg + 4]);
                }
            }
#pragma unroll
            for (int mt = 0; mt < 4; ++mt)
#pragma unroll
                for (int nt = 0; nt < 4; ++nt)
                    mma_tf32(acc[mt][nt], af[mt], bf[nt]);
        }
        __syncthreads();
    }

#pragma unroll
    for (int mt = 0; mt < 4; ++mt) {
        const int row0 = bm + mbase + mt * 16 + gid;
#pragma unroll
        for (int nt = 0; nt < 4; ++nt) {
            const int col = bn + nbase + nt * 8 + tg * 2;
            const float2 bv = *(const float2*)(bias + col);
            float2 v0, v1;
            v0.x = acc[mt][nt][0] + bv.x;  v0.y = acc[mt][nt][1] + bv.y;
            v1.x = acc[mt][nt][2] + bv.x;  v1.y = acc[mt][nt][3] + bv.y;
            *(float2*)(C + (size_t)row0 * NTOT + col)       = v0;
            *(float2*)(C + (size_t)(row0 + 8) * NTOT + col) = v1;
        }
    }
}

// ---------------- sampling ---------------------------------------------------
// block = (b,q); warp = head. Producers (lanes 0-15) pack per-point metadata
// {idx_top, idx_bot, w_top, w_bot} per x-side; gather: half-warp per side,
// 16 lanes x float2 = one 128B row per corner. Output pre-rounded + k-permuted.
__global__ void __launch_bounds__(256)
msda_sample(const float* __restrict__ refp) {
    const int bq   = blockIdx.x;
    const int b    = bq / LEN_Q;
    const int tid  = threadIdx.x;
    const int h    = tid >> 5;
    const int lane = tid & 31;

    __shared__ uint4 s_pk[8][16][2];

    const size_t rowo = (size_t)bq * 256;

    {
        const int ln = lane & 15;           // point id
        const int l  = ln >> 2;             // level

        float logit = g_attn[(size_t)bq * 128 + h * 16 + ln];
        float m = logit;
#pragma unroll
        for (int s = 8; s; s >>= 1) m = fmaxf(m, __shfl_xor_sync(0xffffffffu, m, s, 16));
        float e = __expf(logit - m);
        float ssum = e;
#pragma unroll
        for (int s = 8; s; s >>= 1) ssum += __shfl_xor_sync(0xffffffffu, ssum, s, 16);
        const float aw = e / ssum;

        const int S  = 64 >> l;
        const int st = (l == 0) ? 0 : (l == 1) ? 4096 : (l == 2) ? 5120 : 5376;
        const float fs = (float)S;

        const float rx = refp[(size_t)bq * 8 + l * 2 + 0];
        const float ry = refp[(size_t)bq * 8 + l * 2 + 1];
        const float ox = g_off[rowo + h * 32 + ln * 2 + 0];
        const float oy = g_off[rowo + h * 32 + ln * 2 + 1];

        const float x = fmaf(rx, fs, ox) - 0.5f;
        const float y = fmaf(ry, fs, oy) - 0.5f;
        const float x0f = floorf(x), y0f = floorf(y);
        const int ix0 = (int)x0f, iy0 = (int)y0f;
        const float wx = x - x0f, wy = y - y0f;

        const float fx0 = (unsigned)ix0       < (unsigned)S ? 1.0f : 0.0f;
        const float fx1 = (unsigned)(ix0 + 1) < (unsigned)S ? 1.0f : 0.0f;
        const float fy0 = (unsigned)iy0       < (unsigned)S ? 1.0f : 0.0f;
        const float fy1 = (unsigned)(iy0 + 1) < (unsigned)S ? 1.0f : 0.0f;

        const int cx0 = min(max(ix0, 0), S - 1);
        const int cx1 = min(max(ix0 + 1, 0), S - 1);
        const int cy0 = min(max(iy0, 0), S - 1);
        const int cy1 = min(max(iy0 + 1, 0), S - 1);

        if (lane < 16) {
            uint4 left, right;
            left.x  = (uint32_t)((st + cy0 * S + cx0) * 256);
            left.y  = (uint32_t)((st + cy1 * S + cx0) * 256);
            left.z  = __float_as_uint(aw * (1.0f - wx) * (1.0f - wy) * fx0 * fy0);
            left.w  = __float_as_uint(aw * (1.0f - wx) * wy          * fx0 * fy1);
            right.x = (uint32_t)((st + cy0 * S + cx1) * 256);
            right.y = (uint32_t)((st + cy1 * S + cx1) * 256);
            right.z = __float_as_uint(aw * wx * (1.0f - wy) * fx1 * fy0);
            right.w = __float_as_uint(aw * wx * wy          * fx1 * fy1);
            s_pk[h][ln][0] = left;
            s_pk[h][ln][1] = right;
        }
    }
    __syncwarp();

    const int side = lane >> 4;
    const int cb   = (lane & 15) * 2;       // channel pair within head
    const float* vb = g_value + (size_t)b * (LEN_IN * 256) + h * 32 + cb;

    float a0 = 0.f, a1 = 0.f, a2 = 0.f, a3 = 0.f;
#pragma unroll
    for (int p = 0; p < 16; ++p) {
        const uint4 pk = s_pk[h][p][side];
        const float2 vt = *(const float2*)(vb + pk.x);
        const float2 vo = *(const float2*)(vb + pk.y);
        const float wt = __uint_as_float(pk.z);
        const float wb = __uint_as_float(pk.w);
        a0 = fmaf(wt, vt.x, a0);
        a1 = fmaf(wt, vt.y, a1);
        a2 = fmaf(wb, vo.x, a2);
        a3 = fmaf(wb, vo.y, a3);
    }
    float ox_ = a0 + a2;
    float oy_ = a1 + a3;
    ox_ += __shfl_xor_sync(0xffffffffu, ox_, 16);
    oy_ += __shfl_xor_sync(0xffffffffu, oy_, 16);

    if (lane < 16) {   // store pre-rounded tf32 at k-permuted channel positions
        const int c0 = h * 32 + cb;
        g_mid[rowo + kperm(c0)]     = __uint_as_float(f2tf(ox_));
        g_mid[rowo + kperm(c0 + 1)] = __uint_as_float(f2tf(oy_));
    }
}

// ---------------- launch -----------------------------------------------------
extern "C" void kernel_launch(void* const* d_in, const int* in_sizes, int n_in,
                              void* d_out, int out_size) {
    const float* query   = (const float*)d_in[0];
    const float* refp    = (const float*)d_in[1];
    const float* in_flat = (const float*)d_in[2];
    const float* W_val  = (const float*)d_in[5];
    const float* b_val  = (const float*)d_in[6];
    const float* W_off  = (const float*)d_in[7];
    const float* b_off  = (const float*)d_in[8];
    const float* W_attn = (const float*)d_in[9];
    const float* b_attn = (const float*)d_in[10];
    const float* W_out  = (const float*)d_in[11];
    const float* b_out  = (const float*)d_in[12];
    float* out = (float*)d_out;

    float *pv, *po, *pa, *pm, *wvT, *woT, *waT, *wouT;
    cudaGetSymbolAddress((void**)&pv,  g_value);
    cudaGetSymbolAddress((void**)&po,  g_off);
    cudaGetSymbolAddress((void**)&pa,  g_attn);
    cudaGetSymbolAddress((void**)&pm,  g_mid);
    cudaGetSymbolAddress((void**)&wvT, g_wvT);
    cudaGetSymbolAddress((void**)&woT, g_woT);
    cudaGetSymbolAddress((void**)&waT, g_waT);
    cudaGetSymbolAddress((void**)&wouT, g_wouT);

    cudaFuncSetAttribute(gemm_tc<false>, cudaFuncAttributeMaxDynamicSharedMemorySize, SMEM_B);
    cudaFuncSetAttribute(gemm_tc<true>,  cudaFuncAttributeMaxDynamicSharedMemorySize, SMEM_B);

    transpose_all<<<dim3(64, 4), dim3(32, 8)>>>(W_val, W_off, W_attn, W_out,
                                                wvT, woT, waT, wouT);

    // fused front GEMMs: value (y=0,1), offsets (y=2,3), attn (y=4)
    gemm_tc<false><<<dim3(M_TOTAL / 128, 5), 256, SMEM_B>>>(
        in_flat, query, wvT, woT, waT, b_val, b_off, b_attn, pv, po, pa);

    msda_sample<<<M_TOTAL, 256>>>(refp);

    // output projection (A = g_mid, pre-rounded + k-permuted)
    gemm_tc<true><<<dim3(M_TOTAL / 128, 2), 256, SMEM_B>>>(
        pm, nullptr, wouT, nullptr, nullptr, b_out, nullptr, nullptr,
        out, nullptr, nullptr);
}